// round 3
// baseline (speedup 1.0000x reference)
#include <cuda_runtime.h>
#include <math.h>
#include <stdint.h>

// Problem constants (inputs: [8192, 64] fp32)
#define S        8192
#define E        64
#define CAP      256              // floor(2.0 * 8192 / 64) = 256 (even, >= 4)
#define CHUNK    128
#define NCHUNK   (S / CHUNK)      // 64
#define CB_ELEMS (S * E * CAP)    // 134,217,728

// -------- allocation-free scratch (device globals) --------
__device__ int   g_top1[S];
__device__ int   g_top2[S];
__device__ float g_w1[S];
__device__ float g_w2[S];
__device__ int   g_hist1[NCHUNK * E];
__device__ int   g_hist2[NCHUNK * E];
__device__ int   g_off1[NCHUNK * E];
__device__ int   g_off2[NCHUNK * E];
__device__ int   g_total1[E];

// ---------------------------------------------------------------------------
// Kernel 1: per-token softmax + top1/top2 selection. One warp per token.
// Each lane owns columns {lane, lane+32}. Argmax tie-break = smallest index
// (matches jnp.argmax "first occurrence").
// ---------------------------------------------------------------------------
__global__ void router_kernel(const float* __restrict__ in) {
    int warp = (blockIdx.x * blockDim.x + threadIdx.x) >> 5;
    int lane = threadIdx.x & 31;
    if (warp >= S) return;

    const float* row = in + (size_t)warp * E;
    float x0 = row[lane];
    float x1 = row[lane + 32];

    // ---- top1 argmax ----
    float bv; int bi;
    if (x0 >= x1) { bv = x0; bi = lane; } else { bv = x1; bi = lane + 32; }
#pragma unroll
    for (int o = 16; o > 0; o >>= 1) {
        float ov = __shfl_xor_sync(0xffffffffu, bv, o);
        int   oi = __shfl_xor_sync(0xffffffffu, bi, o);
        if (ov > bv || (ov == bv && oi < bi)) { bv = ov; bi = oi; }
    }
    float m1 = bv;
    int   i1 = bi;

    // ---- softmax denominator (max-subtracted, like jax.nn.softmax) ----
    float sum = expf(x0 - m1) + expf(x1 - m1);
#pragma unroll
    for (int o = 16; o > 0; o >>= 1)
        sum += __shfl_xor_sync(0xffffffffu, sum, o);

    // ---- top2 argmax with top1 index masked to -inf ----
    float y0 = (lane == i1)        ? -INFINITY : x0;
    float y1 = ((lane + 32) == i1) ? -INFINITY : x1;
    float bv2; int bi2;
    if (y0 >= y1) { bv2 = y0; bi2 = lane; } else { bv2 = y1; bi2 = lane + 32; }
#pragma unroll
    for (int o = 16; o > 0; o >>= 1) {
        float ov = __shfl_xor_sync(0xffffffffu, bv2, o);
        int   oi = __shfl_xor_sync(0xffffffffu, bi2, o);
        if (ov > bv2 || (ov == bv2 && oi < bi2)) { bv2 = ov; bi2 = oi; }
    }

    if (lane == 0) {
        g_top1[warp] = i1;
        g_top2[warp] = bi2;
        g_w1[warp]   = 1.0f / sum;              // exp(m1 - m1) / sum
        g_w2[warp]   = expf(bv2 - m1) / sum;
    }
}

// ---------------------------------------------------------------------------
// Kernel 2: per-chunk histograms of top1/top2 expert assignments.
// grid = NCHUNK blocks, block = CHUNK threads; threads [0, E) count.
// ---------------------------------------------------------------------------
__global__ void hist_kernel() {
    __shared__ int s1[CHUNK];
    __shared__ int s2[CHUNK];
    int c = blockIdx.x;
    int t = threadIdx.x;
    s1[t] = g_top1[c * CHUNK + t];
    s2[t] = g_top2[c * CHUNK + t];
    __syncthreads();
    if (t < E) {
        int c1 = 0, c2 = 0;
#pragma unroll 8
        for (int i = 0; i < CHUNK; i++) {
            c1 += (s1[i] == t);
            c2 += (s2[i] == t);
        }
        g_hist1[c * E + t] = c1;
        g_hist2[c * E + t] = c2;
    }
}

// ---------------------------------------------------------------------------
// Kernel 3: exclusive prefix over chunks, per expert. 1 block, E threads.
// Also produces total top1 count per expert (rank2 base offset in reference).
// ---------------------------------------------------------------------------
__global__ void scan_kernel() {
    int e = threadIdx.x;
    int r1 = 0, r2 = 0;
    for (int c = 0; c < NCHUNK; c++) {
        g_off1[c * E + e] = r1;  r1 += g_hist1[c * E + e];
        g_off2[c * E + e] = r2;  r2 += g_hist2[c * E + e];
    }
    g_total1[e] = r1;
}

// ---------------------------------------------------------------------------
// Kernel 4: within-chunk sequential ranking + scatter of nonzero outputs.
// grid = NCHUNK blocks, block = CHUNK threads; threads [0, E) own one expert
// each and walk the 128 chunk tokens in order (preserving cumsum semantics).
// Positions are unique: top2 expert != top1 expert per token; ranks unique
// per expert by construction.
// ---------------------------------------------------------------------------
__global__ void scatter_kernel(float* __restrict__ out, int has_mask) {
    __shared__ int   s1[CHUNK];
    __shared__ int   s2[CHUNK];
    __shared__ float sw1[CHUNK];
    __shared__ float sw2[CHUNK];
    int c = blockIdx.x;
    int t = threadIdx.x;
    int tok = c * CHUNK + t;
    s1[t]  = g_top1[tok];
    s2[t]  = g_top2[tok];
    sw1[t] = g_w1[tok];
    sw2[t] = g_w2[tok];
    __syncthreads();

    if (t < E) {
        const int e = t;
        int ctr1 = g_off1[c * E + e];
        int ctr2 = g_total1[e] + g_off2[c * E + e];
        const size_t MOFF = (size_t)CB_ELEMS;

        for (int i = 0; i < CHUNK; i++) {
            int tk = c * CHUNK + i;
            if (s1[i] == e) {
                int r = ctr1++;
                if (r < CAP) {
                    size_t o = (size_t)tk * (E * CAP) + (size_t)e * CAP + r;
                    out[o] = sw1[i];
                    if (has_mask) out[MOFF + o] = 1.0f;
                }
            }
            if (s2[i] == e) {
                int r = ctr2++;
                if (r < CAP) {
                    size_t o = (size_t)tk * (E * CAP) + (size_t)e * CAP + r;
                    out[o] = sw2[i];
                    if (has_mask) out[MOFF + o] = 1.0f;
                }
            }
        }
    }
}

// ---------------------------------------------------------------------------
extern "C" void kernel_launch(void* const* d_in, const int* in_sizes, int n_in,
                              void* d_out, int out_size) {
    const float* in  = (const float*)d_in[0];
    float*       out = (float*)d_out;

    // Output is ~all zeros (<= 32K nonzeros out of 268M): bulk-zero at HBM
    // write bandwidth, then scatter the nonzeros.
    cudaMemsetAsync(d_out, 0, (size_t)out_size * sizeof(float), 0);

    router_kernel<<<S / 8, 256>>>(in);     // 8 warps/block, warp per token
    hist_kernel<<<NCHUNK, CHUNK>>>();
    scan_kernel<<<1, E>>>();

    // out_size == CB_ELEMS            -> only cb_weight checked
    // out_size == 2*CB_ELEMS          -> cb_weight then sec_mask (as fp32)
    int has_mask = (out_size >= 2 * CB_ELEMS) ? 1 : 0;
    scatter_kernel<<<NCHUNK, CHUNK>>>(out, has_mask);
}

// round 4
// speedup vs baseline: 1.0584x; 1.0584x over previous
#include <cuda_runtime.h>
#include <math.h>
#include <stdint.h>

// Problem constants (inputs: [8192, 64] fp32)
#define S        8192
#define E        64
#define CAP      256              // floor(2.0 * 8192 / 64) = 256
#define CHUNK    128
#define NCHUNK   (S / CHUNK)      // 64
#define ROW      (E * CAP)        // 16384 floats per token row
#define CB_ELEMS (S * E * CAP)    // 134,217,728

// -------- allocation-free scratch (device globals) --------
__device__ int   g_top1[S];
__device__ int   g_top2[S];
__device__ float g_w1[S];
__device__ float g_w2[S];
__device__ int   g_hist1[NCHUNK * E];
__device__ int   g_hist2[NCHUNK * E];
__device__ int   g_off1[NCHUNK * E];
__device__ int   g_off2[NCHUNK * E];
__device__ int   g_total1[E];
__device__ int   g_pos1[S];       // flat e*CAP + rank, or -1 if dropped
__device__ int   g_pos2[S];

// ---------------------------------------------------------------------------
// Kernel 1: per-token softmax + top1/top2. One warp per token, lanes own
// columns {lane, lane+32}. Tie-break = smallest index (jnp.argmax semantics).
// ---------------------------------------------------------------------------
__global__ void router_kernel(const float* __restrict__ in) {
    int warp = (blockIdx.x * blockDim.x + threadIdx.x) >> 5;
    int lane = threadIdx.x & 31;
    if (warp >= S) return;

    const float* row = in + (size_t)warp * E;
    float x0 = row[lane];
    float x1 = row[lane + 32];

    // ---- top1 argmax ----
    float bv; int bi;
    if (x0 >= x1) { bv = x0; bi = lane; } else { bv = x1; bi = lane + 32; }
#pragma unroll
    for (int o = 16; o > 0; o >>= 1) {
        float ov = __shfl_xor_sync(0xffffffffu, bv, o);
        int   oi = __shfl_xor_sync(0xffffffffu, bi, o);
        if (ov > bv || (ov == bv && oi < bi)) { bv = ov; bi = oi; }
    }
    float m1 = bv;
    int   i1 = bi;

    // ---- softmax denominator (max-subtracted) ----
    float sum = expf(x0 - m1) + expf(x1 - m1);
#pragma unroll
    for (int o = 16; o > 0; o >>= 1)
        sum += __shfl_xor_sync(0xffffffffu, sum, o);

    // ---- top2 argmax with top1 index masked to -inf ----
    float y0 = (lane == i1)        ? -INFINITY : x0;
    float y1 = ((lane + 32) == i1) ? -INFINITY : x1;
    float bv2; int bi2;
    if (y0 >= y1) { bv2 = y0; bi2 = lane; } else { bv2 = y1; bi2 = lane + 32; }
#pragma unroll
    for (int o = 16; o > 0; o >>= 1) {
        float ov = __shfl_xor_sync(0xffffffffu, bv2, o);
        int   oi = __shfl_xor_sync(0xffffffffu, bi2, o);
        if (ov > bv2 || (ov == bv2 && oi < bi2)) { bv2 = ov; bi2 = oi; }
    }

    if (lane == 0) {
        g_top1[warp] = i1;
        g_top2[warp] = bi2;
        g_w1[warp]   = 1.0f / sum;
        g_w2[warp]   = expf(bv2 - m1) / sum;
    }
}

// ---------------------------------------------------------------------------
// Kernel 2: per-chunk histograms of top1/top2 expert assignments.
// ---------------------------------------------------------------------------
__global__ void hist_kernel() {
    __shared__ int s1[CHUNK];
    __shared__ int s2[CHUNK];
    int c = blockIdx.x;
    int t = threadIdx.x;
    s1[t] = g_top1[c * CHUNK + t];
    s2[t] = g_top2[c * CHUNK + t];
    __syncthreads();
    if (t < E) {
        int c1 = 0, c2 = 0;
#pragma unroll 8
        for (int i = 0; i < CHUNK; i++) {
            c1 += (s1[i] == t);
            c2 += (s2[i] == t);
        }
        g_hist1[c * E + t] = c1;
        g_hist2[c * E + t] = c2;
    }
}

// ---------------------------------------------------------------------------
// Kernel 3: exclusive prefix over chunks per expert + total top1 counts.
// ---------------------------------------------------------------------------
__global__ void scan_kernel() {
    int e = threadIdx.x;
    int r1 = 0, r2 = 0;
    for (int c = 0; c < NCHUNK; c++) {
        g_off1[c * E + e] = r1;  r1 += g_hist1[c * E + e];
        g_off2[c * E + e] = r2;  r2 += g_hist2[c * E + e];
    }
    g_total1[e] = r1;
}

// ---------------------------------------------------------------------------
// Kernel 4: within-chunk sequential ranking -> per-token flat positions.
// Thread-per-expert walks its chunk's 128 tokens in order (cumsum semantics).
// Each token receives exactly one pos1 write and one pos2 write (-1 = dropped).
// ---------------------------------------------------------------------------
__global__ void pos_kernel() {
    __shared__ int s1[CHUNK];
    __shared__ int s2[CHUNK];
    int c = blockIdx.x;
    int t = threadIdx.x;
    int tok = c * CHUNK + t;
    s1[t] = g_top1[tok];
    s2[t] = g_top2[tok];
    __syncthreads();

    if (t < E) {
        const int e = t;
        int ctr1 = g_off1[c * E + e];
        int ctr2 = g_total1[e] + g_off2[c * E + e];
        for (int i = 0; i < CHUNK; i++) {
            int tk = c * CHUNK + i;
            if (s1[i] == e) {
                int r = ctr1++;
                g_pos1[tk] = (r < CAP) ? (e * CAP + r) : -1;
            }
            if (s2[i] == e) {
                int r = ctr2++;
                g_pos2[tk] = (r < CAP) ? (e * CAP + r) : -1;
            }
        }
    }
}

// ---------------------------------------------------------------------------
// Kernel 5: fused zero-fill + value patch. One block per token row.
// Streams zeros (float4, streaming hint) over both the weight row and the
// mask row, then — after the block-level fence of __syncthreads() — thread 0
// overwrites the <=2 nonzero positions. No cross-block hazards.
// ---------------------------------------------------------------------------
__global__ void __launch_bounds__(256) fill_kernel(float* __restrict__ out,
                                                   int has_mask) {
    int tok = blockIdx.x;
    size_t wbase = (size_t)tok * ROW;
    float4* w4 = (float4*)(out + wbase);
    float4* m4 = (float4*)(out + (size_t)CB_ELEMS + wbase);
    const float4 z = make_float4(0.f, 0.f, 0.f, 0.f);

    if (has_mask) {
#pragma unroll
        for (int i = 0; i < ROW / 4 / 256; i++) {       // 16 iters
            __stcs(&w4[i * 256 + threadIdx.x], z);
            __stcs(&m4[i * 256 + threadIdx.x], z);
        }
    } else {
#pragma unroll
        for (int i = 0; i < ROW / 4 / 256; i++)
            __stcs(&w4[i * 256 + threadIdx.x], z);
    }
    __syncthreads();   // block-level memory fence: zeros ordered before patch

    if (threadIdx.x == 0) {
        int p1 = g_pos1[tok];
        if (p1 >= 0) {
            out[wbase + p1] = g_w1[tok];
            if (has_mask) out[(size_t)CB_ELEMS + wbase + p1] = 1.0f;
        }
        int p2 = g_pos2[tok];
        if (p2 >= 0) {
            out[wbase + p2] = g_w2[tok];
            if (has_mask) out[(size_t)CB_ELEMS + wbase + p2] = 1.0f;
        }
    }
}

// ---------------------------------------------------------------------------
extern "C" void kernel_launch(void* const* d_in, const int* in_sizes, int n_in,
                              void* d_out, int out_size) {
    const float* in  = (const float*)d_in[0];
    float*       out = (float*)d_out;

    router_kernel<<<S / 8, 256>>>(in);     // warp per token
    hist_kernel<<<NCHUNK, CHUNK>>>();
    scan_kernel<<<1, E>>>();
    pos_kernel<<<NCHUNK, CHUNK>>>();

    int has_mask = (out_size >= 2 * CB_ELEMS) ? 1 : 0;
    fill_kernel<<<S, 256>>>(out, has_mask);
}